// round 17
// baseline (speedup 1.0000x reference)
#include <cuda_runtime.h>
#include <stdint.h>

#define BATCH 64
#define INSZ 1024
#define KSZ 1025          // inputs + bias neuron (bias always first: t=1.0 <= X)
#define KPAD 1056         // 132 chunks of 8 (padding: w=0, dx=0 -> provable no-op)
#define CHUNK 8
#define NCHUNK (KPAD / CHUNK)   // 132
#define MSZ 1024
#define THREADS 64
#define MAX_SPIKE 100000.0f

// Scratch: per batch, sorted spike times and per-element quads:
//   (dx, dx, int_bits(row*4096), 0)  — dx duplicated for f32x2 consumption.
__device__ float  g_xs[BATCH][KPAD];
__device__ float4 g_quad[BATCH][KPAD];

// ---- packed f32x2 helpers (per-lane IEEE rn, non-ftz) ---------------------
__device__ __forceinline__ unsigned long long add2(unsigned long long a,
                                                   unsigned long long b) {
    unsigned long long d;
    asm("add.rn.f32x2 %0, %1, %2;" : "=l"(d) : "l"(a), "l"(b));
    return d;
}
__device__ __forceinline__ unsigned long long fma2(unsigned long long a,
                                                   unsigned long long b,
                                                   unsigned long long c) {
    unsigned long long d;
    asm("fma.rn.f32x2 %0, %1, %2, %3;" : "=l"(d) : "l"(a), "l"(b), "l"(c));
    return d;
}
__device__ __forceinline__ float lo2(unsigned long long v) {
    return __uint_as_float((unsigned)v);
}
__device__ __forceinline__ float hi2(unsigned long long v) {
    return __uint_as_float((unsigned)(v >> 32));
}
__device__ __forceinline__ unsigned long long pack2(float a, float b) {
    unsigned long long r;
    asm("mov.b64 %0, {%1, %2};" : "=l"(r) : "f"(a), "f"(b));
    return r;
}
// exact-rounding scalars so the replay is bit-identical to the f32x2 lanes
__device__ __forceinline__ float fadd_rn(float a, float b) {
    float d; asm("add.rn.f32 %0, %1, %2;" : "=f"(d) : "f"(a), "f"(b)); return d;
}
__device__ __forceinline__ float ffma_rn(float a, float b, float c) {
    float d; asm("fma.rn.f32 %0, %1, %2, %3;" : "=f"(d) : "f"(a), "f"(b), "f"(c)); return d;
}

// ---------------------------------------------------------------------------
// Kernel 1: per-batch bitonic sort of the 1024 X values (bias hardcoded at
// slot 0 since bias=1.0 <= min X; tie order provably irrelevant). Strides <=16
// in registers via shfl_xor; strides >=32 via shared memory.
// ---------------------------------------------------------------------------
__global__ void __launch_bounds__(1024) snn_sort_kernel(const float* __restrict__ X) {
    __shared__ unsigned long long sh[1024];
    __shared__ float sx[1025];
    const int b = blockIdx.x;
    const int t = threadIdx.x;

    unsigned long long v =
        ((unsigned long long)__float_as_uint(X[b * INSZ + t]) << 32) | (unsigned)t;

    #pragma unroll 1
    for (int size = 2; size <= 1024; size <<= 1) {
        #pragma unroll 1
        for (int stride = size >> 1; stride >= 32; stride >>= 1) {
            sh[t] = v;
            __syncthreads();
            const unsigned long long u = sh[t ^ stride];
            __syncthreads();
            const bool dir = (t & size) != 0;
            const bool keepmin = (((t & stride) == 0) != dir);
            v = keepmin ? (v < u ? v : u) : (v < u ? u : v);
        }
        const int s0 = (size >> 1) < 16 ? (size >> 1) : 16;
        #pragma unroll 1
        for (int stride = s0; stride >= 1; stride >>= 1) {
            const unsigned long long u = __shfl_xor_sync(0xffffffffu, v, stride);
            const bool dir = (t & size) != 0;
            const bool keepmin = (((t & stride) == 0) != dir);
            v = keepmin ? (v < u ? v : u) : (v < u ? u : v);
        }
    }

    sx[t + 1] = __uint_as_float((unsigned)(v >> 32));
    if (t == 0) sx[0] = 1.0f;
    __syncthreads();

    const int row = (int)(v & 0xffffffffu);
    const int s = t + 1;
    const float x  = sx[s];
    const float xn = (s == KSZ - 1) ? MAX_SPIKE : sx[s + 1];
    const float dx = xn - x;
    g_xs[b][s]   = x;
    g_quad[b][s] = make_float4(dx, dx, __int_as_float(row * (MSZ * 4)), 0.0f);
    if (t == 0) {
        const float dx0 = sx[1] - 1.0f;
        g_xs[b][0]   = 1.0f;
        g_quad[b][0] = make_float4(dx0, dx0, __int_as_float(INSZ * (MSZ * 4)), 0.0f);
    }
    if (t < KPAD - KSZ) {   // padding: w-row = bias row (all zeros), dx = 0
        g_xs[b][KSZ + t]   = MAX_SPIKE;
        g_quad[b][KSZ + t] = make_float4(0.0f, 0.0f,
                                         __int_as_float(INSZ * (MSZ * 4)), 0.0f);
    }
}

// ---------------------------------------------------------------------------
// Kernel 2: packed-f32x2 margin scan, 2 adjacent columns per thread,
// LDG.64 register-ring prefetch (no smem staging, no barriers).
//   cwp_k = cw_k - 1;  G_{k+1} = G_k + cwp_k * dx_k   (G_0 = -x_0 = -1)
// Prefetch (3 chunks ahead): LDS.32(row) + IMAD + LDG.64 -> weight-pair ring.
// Consume per element-pair: LDS.64(dup dx) + FADD2 + FFMA2 + 2x FSETP.
// Per chunk: checkpoint (G, cwp, chunk#) per column while nd; the crossing
// chunk is replayed at the end with bit-exact scalar rn ops:
//   T = x_kf - G_kf / cwp_kf.
// Grid: (MSZ/128, BATCH), 64 threads (matches R15's 512-CTA balance).
// ---------------------------------------------------------------------------
__global__ void __launch_bounds__(THREADS) snn_scan_kernel(
    const float* __restrict__ W, float* __restrict__ out)
{
    __shared__ float4 s_q[KPAD];   // (dx, dx, rowbits, 0) per element, 16.9KB

    const int b = blockIdx.y;
    const int t = threadIdx.x;
    const int mblock = blockIdx.x * 128;
    const int col0 = mblock + 2 * t;
    const char* Wcol = (const char*)W + (size_t)col0 * 4;

    for (int i = t; i < KPAD; i += THREADS)
        s_q[i] = g_quad[b][i];
    __syncthreads();

    unsigned long long wr[4][CHUNK];   // weight-pair ring

    // prefetch one 8-element chunk of weight pairs via LDG.64
    auto load8 = [&](int c, unsigned long long* wdst) {
        const int kb = c * CHUNK;
        #pragma unroll
        for (int u = 0; u < CHUNK; u++) {
            const int rowb = __float_as_int(s_q[kb + u].z);
            wdst[u] = *(const unsigned long long*)(Wcol + rowb);
        }
    };

    load8(0, wr[0]);
    load8(1, wr[1]);
    load8(2, wr[2]);

    unsigned long long cwp2 = pack2(-1.0f, -1.0f);   // cw - THRESHOLD
    unsigned long long G2   = pack2(-1.0f, -1.0f);   // G_0 = -x_0 = -1
    bool  nd0 = true, nd1 = true;
    float Gc0 = -1.0f, cc0 = -1.0f, Gc1 = -1.0f, cc1 = -1.0f;
    int   cb0 = 0, cb1 = 0;

    #pragma unroll 4
    for (int c = 0; c < NCHUNK; c++) {
        // prefetch chunk c+3 (clamped; clamped writes hit never-consumed slots)
        const int pre = (c + 3 < NCHUNK) ? (c + 3) : (NCHUNK - 1);
        load8(pre, wr[(c + 3) & 3]);

        // per-chunk checkpoint per column while not done
        Gc0 = nd0 ? lo2(G2)   : Gc0;
        cc0 = nd0 ? lo2(cwp2) : cc0;
        cb0 = nd0 ? c         : cb0;
        Gc1 = nd1 ? hi2(G2)   : Gc1;
        cc1 = nd1 ? hi2(cwp2) : cc1;
        cb1 = nd1 ? c         : cb1;

        const unsigned long long* wv = wr[c & 3];
        const int kb = c * CHUNK;
        #pragma unroll
        for (int u = 0; u < CHUNK; u++) {
            const unsigned long long dx2 =
                *(const unsigned long long*)(&s_q[kb + u].x);   // (dx, dx) broadcast
            cwp2 = add2(cwp2, wv[u]);
            const unsigned long long Gn2 = fma2(cwp2, dx2, G2);
            nd0 = nd0 && (lo2(Gn2) < 0.0f);
            nd1 = nd1 && (hi2(Gn2) < 0.0f);
            G2 = Gn2;
        }
    }

    // replay the crossing chunk for one column (bit-exact rn arithmetic)
    auto replay = [&](int cb, float Gc, float cc, int colbyte) -> float {
        const int kb = cb * CHUNK;
        float Gr = Gc, cr = cc, res = MAX_SPIKE;
        bool found = false;
        #pragma unroll
        for (int j = 0; j < CHUNK; j++) {
            const float4 q = s_q[kb + j];
            const float w  = *(const float*)((const char*)W +
                                             __float_as_int(q.z) + colbyte);
            const float cn = fadd_rn(cr, w);
            const float Gn = ffma_rn(cn, q.x, Gr);
            if (!found && Gn >= 0.0f) {
                res = g_xs[b][kb + j] - Gr / cn;
                found = true;
            }
            cr = cn; Gr = Gn;
        }
        return res;
    };

    const float r0 = nd0 ? MAX_SPIKE : replay(cb0, Gc0, cc0, col0 * 4);
    const float r1 = nd1 ? MAX_SPIKE : replay(cb1, Gc1, cc1, (col0 + 1) * 4);
    *(float2*)&out[(size_t)b * MSZ + col0] = make_float2(r0, r1);
}

// ---------------------------------------------------------------------------
extern "C" void kernel_launch(void* const* d_in, const int* in_sizes, int n_in,
                              void* d_out, int out_size) {
    const float* X = (const float*)d_in[0];   // [64, 1024] spike times
    const float* W = (const float*)d_in[1];   // [1025, 1024] weights
    float* out = (float*)d_out;               // [64, 1024]

    snn_sort_kernel<<<BATCH, 1024>>>(X);
    snn_scan_kernel<<<dim3(MSZ / 128, BATCH), THREADS>>>(W, out);
}